// round 7
// baseline (speedup 1.0000x reference)
#include <cuda_runtime.h>
#include <cuda_fp16.h>

// ---------------- problem constants ----------------
#define NU 40000
#define NI 20000
#define NN 60000            // NU + NI
#define DD 128
#define NE 320000
#define E2 640000           // directed edges (both directions)
#define NB 4096
#define NSEL (3 * NB)       // 12288 rows needed for the loss

// ---------------- device scratch (static, no allocs) ----------------
__device__ int   g_deg[NN];
__device__ float g_dinv[NN];
__device__ int   g_rs[NN];           // CSR row starts
__device__ int   g_cur[NN];          // fill cursors
__device__ int2  g_edge[E2];         // {col, val_bits} interleaved
// fp16 embeddings: one row = 128 halves = 32 uint2 (8B per lane)
__device__ uint2 g_x0[(size_t)NN * 32];
__device__ uint2 g_x1[(size_t)NN * 32];
__device__ uint2 g_x2[(size_t)NN * 32];
__device__ float4 g_fin[(size_t)NSEL * 32];   // compact final embeddings (fp32)

// ---------------- init: convert inputs to fp16 x0, zero deg & out ----------------
__global__ void k_init(const float4* __restrict__ ue, const float4* __restrict__ ie,
                       float* __restrict__ out) {
    int i = blockIdx.x * blockDim.x + threadIdx.x;   // one float4 (=4 dims) per thread
    const int TOT = NN * DD / 4;                     // 1.92M
    if (i < NN) g_deg[i] = 0;
    if (i == 0) out[0] = 0.f;
    if (i >= TOT) return;
    float4 v = (i < NU * DD / 4) ? __ldg(&ue[i]) : __ldg(&ie[i - NU * DD / 4]);
    __half2 h0 = __float22half2_rn(make_float2(v.x, v.y));
    __half2 h1 = __float22half2_rn(make_float2(v.z, v.w));
    uint2 o;
    o.x = *(unsigned int*)&h0;
    o.y = *(unsigned int*)&h1;
    g_x0[i] = o;
}

__global__ void k_count(const int* __restrict__ au, const int* __restrict__ ai) {
    int i = blockIdx.x * blockDim.x + threadIdx.x;
    if (i >= NE) return;
    atomicAdd(&g_deg[au[i]], 1);
    atomicAdd(&g_deg[ai[i] + NU], 1);
}

// ---- single-block scan: deg -> rs/cur exclusive prefix, plus dinv ----
#define SCAN_THREADS 1024
#define SCAN_CH 59               // 1024*59 = 60416 >= 60000
__global__ __launch_bounds__(SCAN_THREADS) void k_scan() {
    __shared__ int sh[SCAN_THREADS];
    int t = threadIdx.x;
    int base = t * SCAN_CH;

    int s = 0;
    #pragma unroll 4
    for (int i = 0; i < SCAN_CH; i++) {
        int idx = base + i;
        if (idx < NN) s += g_deg[idx];
    }
    sh[t] = s;
    __syncthreads();
    // Hillis-Steele inclusive scan over 1024 partials
    #pragma unroll
    for (int off = 1; off < SCAN_THREADS; off <<= 1) {
        int u = (t >= off) ? sh[t - off] : 0;
        __syncthreads();
        sh[t] += u;
        __syncthreads();
    }
    int run = sh[t] - s;   // exclusive prefix for this chunk
    for (int i = 0; i < SCAN_CH; i++) {
        int idx = base + i;
        if (idx < NN) {
            int d = g_deg[idx];
            g_rs[idx]   = run;
            g_cur[idx]  = run;
            g_dinv[idx] = rsqrtf((float)d + 1e-7f);
            run += d;
        }
    }
}

__global__ void k_fill(const int* __restrict__ au, const int* __restrict__ ai) {
    int i = blockIdx.x * blockDim.x + threadIdx.x;
    if (i >= NE) return;
    int u  = au[i];
    int it = ai[i] + NU;
    float v = g_dinv[u] * g_dinv[it];
    int vb = __float_as_int(v);
    int pu = atomicAdd(&g_cur[u], 1);
    g_edge[pu] = make_int2(it, vb);
    int pi = atomicAdd(&g_cur[it], 1);
    g_edge[pi] = make_int2(u, vb);
}

// ---------------- SpMM helpers ----------------
__device__ __forceinline__ void edge_fma(float2& s0, float2& s1, float v, uint2 w) {
    float2 a = __half22float2(*(__half2*)&w.x);
    float2 b = __half22float2(*(__half2*)&w.y);
    s0.x += v * a.x; s0.y += v * a.y;
    s1.x += v * b.x; s1.y += v * b.y;
}

// Gather one row's SpMM result from source x, fp32 accumulate.
__device__ __forceinline__ void row_gather(const uint2* __restrict__ x,
                                           int row, int lane,
                                           float2& s0, float2& s1) {
    int start = g_rs[row];
    int end   = start + g_deg[row];
    int e = start;
    for (; e + 4 <= end; e += 4) {
        int2 e0 = __ldg(&g_edge[e]);
        int2 e1 = __ldg(&g_edge[e + 1]);
        int2 e2 = __ldg(&g_edge[e + 2]);
        int2 e3 = __ldg(&g_edge[e + 3]);
        uint2 w0 = __ldg(&x[(size_t)e0.x * 32 + lane]);
        uint2 w1 = __ldg(&x[(size_t)e1.x * 32 + lane]);
        uint2 w2 = __ldg(&x[(size_t)e2.x * 32 + lane]);
        uint2 w3 = __ldg(&x[(size_t)e3.x * 32 + lane]);
        edge_fma(s0, s1, __int_as_float(e0.y), w0);
        edge_fma(s0, s1, __int_as_float(e1.y), w1);
        edge_fma(s0, s1, __int_as_float(e2.y), w2);
        edge_fma(s0, s1, __int_as_float(e3.y), w3);
    }
    for (; e < end; e++) {
        int2 ed = __ldg(&g_edge[e]);
        uint2 w = __ldg(&x[(size_t)ed.x * 32 + lane]);
        edge_fma(s0, s1, __int_as_float(ed.y), w);
    }
}

// Full SpMM layer: one warp per row, fp16 in/out.
__global__ __launch_bounds__(256) void k_spmm(int stage) {
    const uint2* __restrict__ x  = (stage == 0) ? g_x0 : g_x1;
    uint2*       __restrict__ xn = (stage == 0) ? g_x1 : g_x2;

    int gw   = (blockIdx.x * blockDim.x + threadIdx.x) >> 5;
    int lane = threadIdx.x & 31;
    if (gw >= NN) return;

    float2 s0 = make_float2(0.f, 0.f);
    float2 s1 = make_float2(0.f, 0.f);
    row_gather(x, gw, lane, s0, s1);

    __half2 h0 = __float22half2_rn(s0);
    __half2 h1 = __float22half2_rn(s1);
    uint2 o;
    o.x = *(unsigned int*)&h0;
    o.y = *(unsigned int*)&h1;
    xn[(size_t)gw * 32 + lane] = o;
}

// Layer-3 SpMM ONLY for rows the loss needs, fused with the 4-layer sum.
// entry idx: [0,NB)=user, [NB,2NB)=pos item, [2NB,3NB)=neg item.
__global__ __launch_bounds__(256) void k_last(const float4* __restrict__ ue4,
                                              const float4* __restrict__ ie4,
                                              const int* __restrict__ user,
                                              const int* __restrict__ pos,
                                              const int* __restrict__ neg) {
    int idx  = (blockIdx.x * blockDim.x + threadIdx.x) >> 5;
    int lane = threadIdx.x & 31;
    if (idx >= NSEL) return;

    int row;
    const float4* base4;
    int brow;
    if (idx < NB)           { brow = user[idx];          row = brow;      base4 = ue4; }
    else if (idx < 2 * NB)  { brow = pos[idx - NB] - 1;  row = NU + brow; base4 = ie4; }
    else                    { brow = neg[idx - 2*NB] - 1; row = NU + brow; base4 = ie4; }

    // layer-3 gather from x2
    float2 s0 = make_float2(0.f, 0.f);
    float2 s1 = make_float2(0.f, 0.f);
    row_gather(g_x2, row, lane, s0, s1);

    // + x0 (fp32 from inputs) + x1 + x2
    float4 r = __ldg(&base4[(size_t)brow * 32 + lane]);
    r.x += s0.x; r.y += s0.y; r.z += s1.x; r.w += s1.y;

    size_t o = (size_t)row * 32 + lane;
    uint2 w1 = __ldg(&g_x1[o]);
    uint2 w2 = __ldg(&g_x2[o]);
    float2 a, b;
    a = __half22float2(*(__half2*)&w1.x); b = __half22float2(*(__half2*)&w1.y);
    r.x += a.x; r.y += a.y; r.z += b.x; r.w += b.y;
    a = __half22float2(*(__half2*)&w2.x); b = __half22float2(*(__half2*)&w2.y);
    r.x += a.x; r.y += a.y; r.z += b.x; r.w += b.y;

    g_fin[(size_t)idx * 32 + lane] = r;
}

// Score: one warp per batch element; compact contiguous reads from g_fin.
__global__ void k_score(float* __restrict__ out) {
    int gw   = (blockIdx.x * blockDim.x + threadIdx.x) >> 5;
    int lane = threadIdx.x & 31;
    if (gw >= NB) return;

    float4 tu = __ldg(&g_fin[(size_t)gw * 32 + lane]);
    float4 pi = __ldg(&g_fin[(size_t)(NB + gw) * 32 + lane]);
    float4 ni = __ldg(&g_fin[(size_t)(2 * NB + gw) * 32 + lane]);

    float s = tu.x * (pi.x - ni.x) + tu.y * (pi.y - ni.y)
            + tu.z * (pi.z - ni.z) + tu.w * (pi.w - ni.w);
    #pragma unroll
    for (int off = 16; off; off >>= 1)
        s += __shfl_xor_sync(0xffffffffu, s, off);

    if (lane == 0) {
        float diff = s * (1.f / 16.f);          // ((sum)/4)·((sum)/4)
        float t = -diff;                        // softplus(-diff) = -log sigmoid(diff)
        float term = fmaxf(t, 0.f) + log1pf(expf(-fabsf(t)));
        atomicAdd(out, term * (1.f / (float)NB));
    }
}

// ---------------- launch ----------------
extern "C" void kernel_launch(void* const* d_in, const int* in_sizes, int n_in,
                              void* d_out, int out_size) {
    const float* ue  = (const float*)d_in[0];
    const float* ie  = (const float*)d_in[1];
    const int*   au  = (const int*)d_in[2];
    const int*   ai  = (const int*)d_in[3];
    const int*   usr = (const int*)d_in[4];
    const int*   pos = (const int*)d_in[5];
    const int*   neg = (const int*)d_in[6];
    float*       out = (float*)d_out;

    k_init <<<(NN * DD / 4 + 255) / 256, 256>>>((const float4*)ue, (const float4*)ie, out);
    k_count<<<(NE + 255) / 256, 256>>>(au, ai);
    k_scan <<<1, SCAN_THREADS>>>();
    k_fill <<<(NE + 255) / 256, 256>>>(au, ai);

    const int SPMM_BLOCKS = (NN * 32 + 255) / 256;   // one warp per row
    k_spmm<<<SPMM_BLOCKS, 256>>>(0);   // x0 -> x1
    k_spmm<<<SPMM_BLOCKS, 256>>>(1);   // x1 -> x2
    k_last<<<(NSEL * 32 + 255) / 256, 256>>>((const float4*)ue, (const float4*)ie,
                                             usr, pos, neg);
    k_score<<<(NB * 32 + 255) / 256, 256>>>(out);
}